// round 9
// baseline (speedup 1.0000x reference)
#include <cuda_runtime.h>
#include <math.h>
#include <mma.h>

using namespace nvcuda;

// ---------------- sizes ----------------
#define BATCH 16
#define H0 256
#define W0 256
#define CIN 3
#define HID 128
#define EMB 64
#define KCODES 1024
#define H1v 128
#define W1v 128
#define H2v 64
#define W2v 64

#define XREC_ELEMS (BATCH*H0*W0*3)      // 3145728
#define TOK_OFF    XREC_ELEMS
#define TOK_ELEMS  (BATCH*H2v*W2v)      // 65536
#define LOSS_OFF   (TOK_OFF + TOK_ELEMS)

typedef unsigned long long u64;

// ---------------- scratch ----------------
__device__ float g_h1[BATCH*H1v*W1v*HID];   // encoder conv1 out (gelu'd)
__device__ float g_ze[BATCH*H2v*W2v*EMB];   // z_e
__device__ float g_zst[BATCH*H2v*W2v*EMB];  // z_st
__device__ float g_g1[BATCH*H1v*W1v*HID];   // decoder convt1 out (gelu'd)
__device__ float g_wt1[1024*128];           // dec_w1 tf32-rounded
__device__ float g_wt2[2048*128];           // dec_w2 tf32-rounded
__device__ float g_w2h[2048*128];           // enc_w2 tf32 high
__device__ float g_w2l[2048*128];           // enc_w2 tf32 low
__device__ float g_loss;

__device__ __forceinline__ float gelu_f(float x) {
    float t = 0.7978845608028654f * (x + 0.044715f * x * x * x);
    return 0.5f * x * (1.0f + tanhf(t));
}
__device__ __forceinline__ float tf32r(float x) { return wmma::__float_to_tf32(x); }

// ---------------- packed f32x2 helpers ----------------
__device__ __forceinline__ u64 splat2(float a) {
    u64 r; asm("mov.b64 %0, {%1, %1};" : "=l"(r) : "f"(a)); return r;
}
__device__ __forceinline__ u64 pack2(float lo, float hi) {
    u64 r; asm("mov.b64 %0, {%1, %2};" : "=l"(r) : "f"(lo), "f"(hi)); return r;
}
__device__ __forceinline__ void unpack2(u64 v, float& lo, float& hi) {
    asm("mov.b64 {%0, %1}, %2;" : "=f"(lo), "=f"(hi) : "l"(v));
}
__device__ __forceinline__ void ffma2(u64& d, u64 a, u64 b) {
    asm("fma.rn.f32x2 %0, %1, %2, %0;" : "+l"(d) : "l"(a), "l"(b));
}

// ================= prep: tf32 round / split =================
__global__ void k_prep_tf32(const float* __restrict__ w, float* __restrict__ o, int n) {
    int i = blockIdx.x * 256 + threadIdx.x;
    if (i < n) o[i] = tf32r(w[i]);
}
__global__ void k_prep_split(const float* __restrict__ w, float* __restrict__ oh,
                             float* __restrict__ ol, int n) {
    int i = blockIdx.x * 256 + threadIdx.x;
    if (i < n) {
        float a = w[i];
        float ah = tf32r(a);
        oh[i] = ah;
        ol[i] = tf32r(a - ah);
    }
}

// ================= conv1: x -> h1, 4x4 s2 SAME, gelu (fp32) =================
__global__ void k_conv1(const float* __restrict__ x, const float* __restrict__ w,
                        const float* __restrict__ b) {
    __shared__ float ws[4*4*3*128];
    __shared__ float ins[4*34*3];
    int tid = threadIdx.x;
    int bx = blockIdx.x, oy = blockIdx.y, n = blockIdx.z;
    if (bx == 0 && oy == 0 && n == 0 && tid == 0) g_loss = 0.0f;
    for (int i = tid; i < 6144; i += 128) ws[i] = w[i];
    int x0 = bx * 16;
    for (int i = tid; i < 4*34*3; i += 128) {
        int r = i / (34*3); int rem = i - r*(34*3); int c = rem / 3; int ch = rem % 3;
        int gy = 2*oy - 1 + r;
        int gx = 2*x0 - 1 + c;
        float v = 0.0f;
        if (gy >= 0 && gy < H0 && gx >= 0 && gx < W0) v = x[((n*H0+gy)*W0+gx)*CIN + ch];
        ins[i] = v;
    }
    __syncthreads();
    int co = tid;
    float bias = b[co];
    u64 acc2[8];
#pragma unroll
    for (int pp = 0; pp < 8; pp++) acc2[pp] = pack2(bias, bias);
    for (int ky = 0; ky < 4; ky++) {
        for (int kx = 0; kx < 4; kx++) {
#pragma unroll
            for (int ci = 0; ci < 3; ci++) {
                float wv = ws[((ky*4+kx)*3+ci)*128 + co];
                u64 wvv = splat2(wv);
#pragma unroll
                for (int pp = 0; pp < 8; pp++) {
                    u64 av = pack2(ins[(ky*34 + 4*pp + kx)*3 + ci],
                                   ins[(ky*34 + 4*pp + 2 + kx)*3 + ci]);
                    ffma2(acc2[pp], av, wvv);
                }
            }
        }
    }
#pragma unroll
    for (int pp = 0; pp < 8; pp++) {
        float v0, v1; unpack2(acc2[pp], v0, v1);
        g_h1[((n*H1v+oy)*W1v + x0 + 2*pp)*HID + co]     = gelu_f(v0);
        g_h1[((n*H1v+oy)*W1v + x0 + 2*pp + 1)*HID + co] = gelu_f(v1);
    }
}

// ================= conv2 WMMA 3xtf32 + gelu + 1x1: h1 -> z_e =================
// M=128 (2 out rows x 64 px), N=128 co, K=2048 in 64 chunks of 32.
// grid (1, 32, 16), block 256 = 8 warps (4m x 2n).
__global__ void __launch_bounds__(256, 2) k_conv2_wmma(
    const float* __restrict__ wh, const float* __restrict__ wl,
    const float* __restrict__ b2,
    const float* __restrict__ w3, const float* __restrict__ b3)
{
    extern __shared__ float smf[];
    float* Ah  = smf;              // 128*36 = 4608
    float* Al  = smf + 4608;       // 4608
    float* Bh  = smf + 9216;       // 32*132 = 4224
    float* Bl  = smf + 13440;      // 4224
    float* b2s = smf + 17664;      // 128
    float* b3s = smf + 17792;      // 64
    float* Cs  = smf;              // epilogue reuse [128][132]

    int tid = threadIdx.x;
    int pr = blockIdx.y, n = blockIdx.z;
    int oy0 = pr * 2;

    for (int i = tid; i < 128; i += 256) b2s[i] = b2[i];
    if (tid < 64) b3s[tid] = b3[tid];

    int wid = tid >> 5;
    int m0 = (wid & 3) * 32;
    int n0 = (wid >> 2) * 64;

    wmma::fragment<wmma::accumulator, 16, 16, 8, float> acc[2][4];
#pragma unroll
    for (int im = 0; im < 2; im++)
#pragma unroll
        for (int in = 0; in < 4; in++) wmma::fill_fragment(acc[im][in], 0.0f);

#pragma unroll 1
    for (int c = 0; c < 64; c++) {
        int tap = c >> 2;
        int ci0 = (c & 3) * 32;
        int ky = tap >> 2, kx = tap & 3;
        __syncthreads();
        // stage A (split high/low): 128 rows x 32 floats
#pragma unroll
        for (int q = 0; q < 4; q++) {
            int u = tid + q*256;
            int m = u >> 3, c8 = u & 7;
            int h = m >> 6, j = m & 63;
            int iy = 2*(oy0 + h) - 1 + ky;
            int ix = 2*j - 1 + kx;
            float4 v = make_float4(0,0,0,0);
            if (iy >= 0 && iy < H1v && ix >= 0 && ix < W1v)
                v = *reinterpret_cast<const float4*>(
                    &g_h1[((size_t)((n*H1v + iy)*W1v + ix))*HID + ci0 + 4*c8]);
            float4 vh, vl;
            vh.x = tf32r(v.x); vl.x = tf32r(v.x - vh.x);
            vh.y = tf32r(v.y); vl.y = tf32r(v.y - vh.y);
            vh.z = tf32r(v.z); vl.z = tf32r(v.z - vh.z);
            vh.w = tf32r(v.w); vl.w = tf32r(v.w - vh.w);
            *reinterpret_cast<float4*>(&Ah[m*36 + 4*c8]) = vh;
            *reinterpret_cast<float4*>(&Al[m*36 + 4*c8]) = vl;
        }
        // stage B (pre-split): 32 k-rows x 128 co
#pragma unroll
        for (int q = 0; q < 4; q++) {
            int u = tid + q*256;
            int kk = u >> 5, c32 = u & 31;
            size_t go = ((size_t)(tap*HID + ci0 + kk))*128 + 4*c32;
            *reinterpret_cast<float4*>(&Bh[kk*132 + 4*c32]) =
                *reinterpret_cast<const float4*>(&wh[go]);
            *reinterpret_cast<float4*>(&Bl[kk*132 + 4*c32]) =
                *reinterpret_cast<const float4*>(&wl[go]);
        }
        __syncthreads();
#pragma unroll
        for (int ks = 0; ks < 4; ks++) {
            int kk = ks * 8;
            wmma::fragment<wmma::matrix_a, 16, 16, 8, wmma::precision::tf32, wmma::row_major> ahf[2], alf[2];
#pragma unroll
            for (int im = 0; im < 2; im++) {
                wmma::load_matrix_sync(ahf[im], &Ah[(m0 + 16*im)*36 + kk], 36);
                wmma::load_matrix_sync(alf[im], &Al[(m0 + 16*im)*36 + kk], 36);
            }
#pragma unroll
            for (int in = 0; in < 4; in++) {
                wmma::fragment<wmma::matrix_b, 16, 16, 8, wmma::precision::tf32, wmma::row_major> bhf, blf;
                wmma::load_matrix_sync(bhf, &Bh[kk*132 + n0 + 16*in], 132);
                wmma::load_matrix_sync(blf, &Bl[kk*132 + n0 + 16*in], 132);
#pragma unroll
                for (int im = 0; im < 2; im++) {
                    wmma::mma_sync(acc[im][in], alf[im], bhf, acc[im][in]);
                    wmma::mma_sync(acc[im][in], ahf[im], blf, acc[im][in]);
                    wmma::mma_sync(acc[im][in], ahf[im], bhf, acc[im][in]);
                }
            }
        }
    }
    __syncthreads();
#pragma unroll
    for (int im = 0; im < 2; im++)
#pragma unroll
        for (int in = 0; in < 4; in++)
            wmma::store_matrix_sync(&Cs[(m0 + 16*im)*132 + n0 + 16*in],
                                    acc[im][in], 132, wmma::mem_row_major);
    __syncthreads();
    // bias + gelu in place
    for (int i = tid; i < 128*128; i += 256) {
        int px = i >> 7, ci = i & 127;
        Cs[px*132 + ci] = gelu_f(Cs[px*132 + ci] + b2s[ci]);
    }
    __syncthreads();
    // fused 1x1: 128 -> 64
    {
        int px = tid >> 1;
        int e0 = (tid & 1) * 32;
        u64 z2[16];
#pragma unroll
        for (int u = 0; u < 8; u++) {
            float b0 = b3s[e0 + 4*u], b1 = b3s[e0 + 4*u + 1];
            float b2f = b3s[e0 + 4*u + 2], b3f = b3s[e0 + 4*u + 3];
            z2[2*u]   = pack2(b0, b1);
            z2[2*u+1] = pack2(b2f, b3f);
        }
#pragma unroll 4
        for (int ci = 0; ci < 128; ci++) {
            float hv = Cs[px*132 + ci];
            u64 s = splat2(hv);
#pragma unroll
            for (int u = 0; u < 8; u++) {
                float4 wv = *reinterpret_cast<const float4*>(&w3[ci*EMB + e0 + 4*u]);
                ffma2(z2[2*u],   s, pack2(wv.x, wv.y));
                ffma2(z2[2*u+1], s, pack2(wv.z, wv.w));
            }
        }
        int row = oy0 + (px >> 6), col = px & 63;
        float* dst = &g_ze[((size_t)((n*H2v + row)*W2v + col))*EMB + e0];
#pragma unroll
        for (int u = 0; u < 8; u++) {
            float f0,f1,f2,f3;
            unpack2(z2[2*u], f0, f1); unpack2(z2[2*u+1], f2, f3);
            *reinterpret_cast<float4*>(dst + 4*u) = make_float4(f0, f1, f2, f3);
        }
    }
}

// ================= VQ =================
#define CSTR 68
__global__ void k_vq(const float* __restrict__ cb, float* __restrict__ dout) {
    __shared__ float cs[64*CSTR];
    __shared__ float e2s[64];
    __shared__ float bval[128];
    __shared__ int   bidx[128];
    __shared__ int   widx[16];
    __shared__ float lred[128];
    int tid = threadIdx.x;
    int pb = blockIdx.x * 16;
    int p = tid & 15;
    int g = tid >> 4;
    float4 z4[16];
    const float* zp = &g_ze[(pb + p)*EMB];
#pragma unroll
    for (int i = 0; i < 16; i++) z4[i] = *reinterpret_cast<const float4*>(&zp[4*i]);
    float best = 3.4e38f; int bi = 0;
    for (int ch = 0; ch < 16; ch++) {
        for (int i = tid; i < 64*16; i += 128) {
            int cj = i >> 4; int d4 = i & 15;
            float4 v = *reinterpret_cast<const float4*>(&cb[(ch*64+cj)*EMB + 4*d4]);
            *reinterpret_cast<float4*>(&cs[cj*CSTR + 4*d4]) = v;
        }
        __syncthreads();
        if (tid < 64) {
            float s = 0.0f;
#pragma unroll 8
            for (int d = 0; d < 64; d++) { float c = cs[tid*CSTR + d]; s = fmaf(c, c, s); }
            e2s[tid] = s;
        }
        __syncthreads();
#pragma unroll
        for (int j = 0; j < 8; j++) {
            int cj = g*8 + j;
            const float* cp = &cs[cj*CSTR];
            float dot = 0.0f;
#pragma unroll
            for (int i = 0; i < 16; i++) {
                float4 c = *reinterpret_cast<const float4*>(&cp[4*i]);
                dot = fmaf(z4[i].x, c.x, dot); dot = fmaf(z4[i].y, c.y, dot);
                dot = fmaf(z4[i].z, c.z, dot); dot = fmaf(z4[i].w, c.w, dot);
            }
            float dist = e2s[cj] - 2.0f*dot;
            int gidx = ch*64 + cj;
            if (dist < best || (dist == best && gidx < bi)) { best = dist; bi = gidx; }
        }
        __syncthreads();
    }
    bval[tid] = best; bidx[tid] = bi;
    __syncthreads();
    if (tid < 16) {
        float bb = bval[tid]; int bbi = bidx[tid];
        for (int k = 1; k < 8; k++) {
            float v = bval[tid + 16*k]; int vi = bidx[tid + 16*k];
            if (v < bb || (v == bb && vi < bbi)) { bb = v; bbi = vi; }
        }
        widx[tid] = bbi;
        dout[TOK_OFF + pb + tid] = (float)bbi;
    }
    __syncthreads();
    int idx = widx[p];
    float lsum = 0.0f;
    const float* cq = &cb[idx*EMB + g*8];
    const float* ze = &g_ze[(pb + p)*EMB + g*8];
    float*       zs = &g_zst[(pb + p)*EMB + g*8];
#pragma unroll
    for (int d = 0; d < 8; d++) {
        float zq = cq[d]; float z = ze[d];
        float diff = zq - z;
        zs[d] = z + diff;
        lsum = fmaf(diff, diff, lsum);
    }
    lred[tid] = lsum;
    __syncthreads();
    for (int s = 64; s > 0; s >>= 1) {
        if (tid < s) lred[tid] += lred[tid + s];
        __syncthreads();
    }
    if (tid == 0) atomicAdd(&g_loss, lred[0]);
}

// ================= WMMA tf32 transposed-conv (K=64 chunks, pre-converted) ===
// CTA: one parity tile. M=128 (2 out rows x 64 same-parity px), N=128 co,
// K = 2kyi*2kxi*CI in chunks of 64. 256 threads = 8 warps (4m x 2n).
template<int CI, int HIN, int WIN, bool RGB>
__global__ void __launch_bounds__(256, 2) k_convt_wmma(
    const float* __restrict__ src, const float* __restrict__ wt,
    const float* __restrict__ bias,
    const float* __restrict__ w3, const float* __restrict__ b3,
    float* __restrict__ dst)
{
    constexpr int CIC64 = CI / 64;
    constexpr int NCH   = 4 * CIC64;
    constexpr int HOUT  = 2 * HIN;
    constexpr int WOUT  = 2 * WIN;

    extern __shared__ float smf[];
    float* As    = smf;             // 128*68 = 8704
    float* Bs    = smf + 8704;      // 64*132 = 8448
    float* Cs    = smf;             // epilogue reuse: 128*132 = 16896
    float* biass = smf + 17152;     // 128
    float* w3s   = smf + 17280;     // 384
    float* b3s   = smf + 17664;     // 3

    int tid = threadIdx.x;
    int bx = blockIdx.x, pr = blockIdx.y, n = blockIdx.z;
    int t  = bx & 1;
    int xh = bx >> 1;
    int oy = 4*(pr >> 1) + (pr & 1);          // rows oy, oy+2
    int x0 = xh * 128;
    int xhalf = x0 >> 1;
    int kyA = oy & 1;
    int iy0 = (oy + kyA - 2) >> 1;

    for (int i = tid; i < 128; i += 256) biass[i] = bias[i];
    if (RGB) {
        for (int i = tid; i < 384; i += 256) w3s[i] = w3[i];
        if (tid < 3) b3s[tid] = b3[tid];
    }

    int wid = tid >> 5;
    int m0 = (wid & 3) * 32;
    int n0 = (wid >> 2) * 64;

    wmma::fragment<wmma::accumulator, 16, 16, 8, float> acc[2][4];
#pragma unroll
    for (int im = 0; im < 2; im++)
#pragma unroll
        for (int in = 0; in < 4; in++) wmma::fill_fragment(acc[im][in], 0.0f);

#pragma unroll 1
    for (int c = 0; c < NCH; c++) {
        int kyi = c / (2*CIC64);
        int kxi = (c / CIC64) & 1;
        int ci0 = (c % CIC64) * 64;
        __syncthreads();
        // stage A: 128 rows x 64 floats, tf32-rounded at store
        {
            int xb = xhalf + t + kxi - 1;
#pragma unroll
            for (int q = 0; q < 8; q++) {
                int u = tid + q*256;
                int m = u >> 4, c16 = u & 15;
                int h = m >> 6, j = m & 63;
                int y = iy0 + h + kyi;
                int col = xb + j;
                float4 v = make_float4(0,0,0,0);
                if (y >= 0 && y < HIN && col >= 0 && col < WIN)
                    v = *reinterpret_cast<const float4*>(
                        &src[((size_t)((n*HIN + y)*WIN + col))*CI + ci0 + 4*c16]);
                v.x = tf32r(v.x); v.y = tf32r(v.y); v.z = tf32r(v.z); v.w = tf32r(v.w);
                *reinterpret_cast<float4*>(&As[m*68 + 4*c16]) = v;
            }
        }
        // stage B: 64 k-rows x 128 co (pre-rounded weights)
        {
            int k0 = ((kyA + 2*kyi)*4 + (t + 2*kxi))*CI + ci0;
#pragma unroll
            for (int q = 0; q < 8; q++) {
                int u = tid + q*256;
                int kk = u >> 5, c32 = u & 31;
                float4 v = *reinterpret_cast<const float4*>(&wt[(size_t)(k0 + kk)*128 + 4*c32]);
                *reinterpret_cast<float4*>(&Bs[kk*132 + 4*c32]) = v;
            }
        }
        __syncthreads();
#pragma unroll
        for (int ks = 0; ks < 8; ks++) {
            int kk = ks * 8;
            wmma::fragment<wmma::matrix_a, 16, 16, 8, wmma::precision::tf32, wmma::row_major> af[2];
#pragma unroll
            for (int im = 0; im < 2; im++)
                wmma::load_matrix_sync(af[im], &As[(m0 + 16*im)*68 + kk], 68);
#pragma unroll
            for (int in = 0; in < 4; in++) {
                wmma::fragment<wmma::matrix_b, 16, 16, 8, wmma::precision::tf32, wmma::row_major> bf;
                wmma::load_matrix_sync(bf, &Bs[kk*132 + n0 + 16*in], 132);
#pragma unroll
                for (int im = 0; im < 2; im++)
                    wmma::mma_sync(acc[im][in], af[im], bf, acc[im][in]);
            }
        }
    }
    __syncthreads();
#pragma unroll
    for (int im = 0; im < 2; im++)
#pragma unroll
        for (int in = 0; in < 4; in++)
            wmma::store_matrix_sync(&Cs[(m0 + 16*im)*132 + n0 + 16*in],
                                    acc[im][in], 132, wmma::mem_row_major);
    __syncthreads();
    // epilogue
    {
        int m = tid >> 1;
        int half = tid & 1;
        int h = m >> 6, j = m & 63;
        int row = oy + 2*h;
        int ox = x0 + 2*j + t;
        const float* cp = &Cs[m*132 + half*64];
        if (RGB) {
            float r = 0.0f, g = 0.0f, bl = 0.0f;
#pragma unroll 8
            for (int kk = 0; kk < 64; kk++) {
                int cc = half*64 + kk;
                float gv = gelu_f(cp[kk] + biass[cc]);
                r  = fmaf(gv, w3s[cc*3+0], r);
                g  = fmaf(gv, w3s[cc*3+1], g);
                bl = fmaf(gv, w3s[cc*3+2], bl);
            }
            r  += __shfl_xor_sync(0xffffffffu, r, 1);
            g  += __shfl_xor_sync(0xffffffffu, g, 1);
            bl += __shfl_xor_sync(0xffffffffu, bl, 1);
            if (half == 0) {
                float* dp = dst + ((size_t)((n*HOUT + row)*WOUT + ox))*3;
                dp[0] = r + b3s[0];
                dp[1] = g + b3s[1];
                dp[2] = bl + b3s[2];
            }
        } else {
            float* dp = dst + ((size_t)((n*HOUT + row)*WOUT + ox))*128 + half*64;
#pragma unroll
            for (int k4 = 0; k4 < 16; k4++) {
                float4 o;
                o.x = gelu_f(cp[4*k4+0] + biass[half*64 + 4*k4+0]);
                o.y = gelu_f(cp[4*k4+1] + biass[half*64 + 4*k4+1]);
                o.z = gelu_f(cp[4*k4+2] + biass[half*64 + 4*k4+2]);
                o.w = gelu_f(cp[4*k4+3] + biass[half*64 + 4*k4+3]);
                *reinterpret_cast<float4*>(dp + 4*k4) = o;
            }
        }
    }
}

// ================= finalize losses =================
__global__ void k_final(float* __restrict__ dout) {
    float l = g_loss / (float)(TOK_ELEMS * EMB);
    dout[LOSS_OFF]     = l;
    dout[LOSS_OFF + 1] = l;
}

// ================= launch =================
extern "C" void kernel_launch(void* const* d_in, const int* in_sizes, int n_in,
                              void* d_out, int out_size) {
    const float* x      = (const float*)d_in[0];
    const float* enc_w1 = (const float*)d_in[1];
    const float* enc_b1 = (const float*)d_in[2];
    const float* enc_w2 = (const float*)d_in[3];
    const float* enc_b2 = (const float*)d_in[4];
    const float* enc_w3 = (const float*)d_in[5];
    const float* enc_b3 = (const float*)d_in[6];
    const float* cb     = (const float*)d_in[7];
    const float* dec_w1 = (const float*)d_in[8];
    const float* dec_b1 = (const float*)d_in[9];
    const float* dec_w2 = (const float*)d_in[10];
    const float* dec_b2 = (const float*)d_in[11];
    const float* dec_w3 = (const float*)d_in[12];
    const float* dec_b3 = (const float*)d_in[13];
    float* out = (float*)d_out;

    float* wt1p; cudaGetSymbolAddress((void**)&wt1p, g_wt1);
    float* wt2p; cudaGetSymbolAddress((void**)&wt2p, g_wt2);
    float* w2hp; cudaGetSymbolAddress((void**)&w2hp, g_w2h);
    float* w2lp; cudaGetSymbolAddress((void**)&w2lp, g_w2l);
    float* zstp; cudaGetSymbolAddress((void**)&zstp, g_zst);
    float* g1p;  cudaGetSymbolAddress((void**)&g1p, g_g1);

    const int smem_dec = 17667 * 4;   // 70668 B
    const int smem_c2  = 17856 * 4;   // 71424 B
    static int smem_set = 0;
    if (!smem_set) {
        cudaFuncSetAttribute(k_convt_wmma<64, 64, 64, false>,
                             cudaFuncAttributeMaxDynamicSharedMemorySize, smem_dec);
        cudaFuncSetAttribute(k_convt_wmma<128, 128, 128, true>,
                             cudaFuncAttributeMaxDynamicSharedMemorySize, smem_dec);
        cudaFuncSetAttribute(k_conv2_wmma,
                             cudaFuncAttributeMaxDynamicSharedMemorySize, smem_c2);
        smem_set = 1;
    }

    k_prep_tf32<<<512, 256>>>(dec_w1, wt1p, 131072);
    k_prep_tf32<<<1024, 256>>>(dec_w2, wt2p, 262144);
    k_prep_split<<<1024, 256>>>(enc_w2, w2hp, w2lp, 262144);

    k_conv1<<<dim3(8, 128, 16), 128>>>(x, enc_w1, enc_b1);
    k_conv2_wmma<<<dim3(1, 32, 16), 256, smem_c2>>>(w2hp, w2lp, enc_b2, enc_w3, enc_b3);
    k_vq<<<4096, 128>>>(cb, out);

    k_convt_wmma<64, 64, 64, false><<<dim3(2, 64, 16), 256, smem_dec>>>(
        zstp, wt1p, dec_b1, nullptr, nullptr, g1p);
    k_convt_wmma<128, 128, 128, true><<<dim3(4, 128, 16), 256, smem_dec>>>(
        g1p, wt2p, dec_b2, dec_w3, dec_b3, out);
    k_final<<<1, 1>>>(out);
}

// round 10
// speedup vs baseline: 1.1565x; 1.1565x over previous
#include <cuda_runtime.h>
#include <math.h>
#include <mma.h>

using namespace nvcuda;

// ---------------- sizes ----------------
#define BATCH 16
#define H0 256
#define W0 256
#define CIN 3
#define HID 128
#define EMB 64
#define KCODES 1024
#define H1v 128
#define W1v 128
#define H2v 64
#define W2v 64

#define XREC_ELEMS (BATCH*H0*W0*3)      // 3145728
#define TOK_OFF    XREC_ELEMS
#define TOK_ELEMS  (BATCH*H2v*W2v)      // 65536
#define LOSS_OFF   (TOK_OFF + TOK_ELEMS)

typedef unsigned long long u64;

// ---------------- scratch ----------------
__device__ float g_h1[BATCH*H1v*W1v*HID];   // encoder conv1 out (gelu'd)
__device__ float g_ze[BATCH*H2v*W2v*EMB];   // z_e
__device__ float g_zst[BATCH*H2v*W2v*EMB];  // z_st
__device__ float g_g1[BATCH*H1v*W1v*HID];   // decoder convt1 out (gelu'd)
__device__ float g_wt1[1024*128];           // dec_w1 tf32-rounded
__device__ float g_wt2[2048*128];           // dec_w2 tf32-rounded
__device__ float g_loss;

__device__ __forceinline__ float gelu_f(float x) {
    float t = 0.7978845608028654f * (x + 0.044715f * x * x * x);
    return 0.5f * x * (1.0f + tanhf(t));
}
__device__ __forceinline__ float tf32r(float x) { return wmma::__float_to_tf32(x); }

// ---------------- packed f32x2 helpers ----------------
__device__ __forceinline__ u64 splat2(float a) {
    u64 r; asm("mov.b64 %0, {%1, %1};" : "=l"(r) : "f"(a)); return r;
}
__device__ __forceinline__ u64 pack2(float lo, float hi) {
    u64 r; asm("mov.b64 %0, {%1, %2};" : "=l"(r) : "f"(lo), "f"(hi)); return r;
}
__device__ __forceinline__ void unpack2(u64 v, float& lo, float& hi) {
    asm("mov.b64 {%0, %1}, %2;" : "=f"(lo), "=f"(hi) : "l"(v));
}
__device__ __forceinline__ void ffma2(u64& d, u64 a, u64 b) {
    asm("fma.rn.f32x2 %0, %1, %2, %0;" : "+l"(d) : "l"(a), "l"(b));
}
#define FFMA2_8(J, AJ) { u64 s_ = splat2(AJ); \
    ffma2(acc2[J][0], s_, w01); ffma2(acc2[J][1], s_, w23); \
    ffma2(acc2[J][2], s_, w45); ffma2(acc2[J][3], s_, w67); }

// ================= prep: tf32 round =================
__global__ void k_prep_tf32(const float* __restrict__ w, float* __restrict__ o, int n) {
    int i = blockIdx.x * 256 + threadIdx.x;
    if (i < n) o[i] = tf32r(w[i]);
}

// ================= conv1: x -> h1, 4x4 s2 SAME, gelu (fp32) =================
__global__ void k_conv1(const float* __restrict__ x, const float* __restrict__ w,
                        const float* __restrict__ b) {
    __shared__ float ws[4*4*3*128];
    __shared__ float ins[4*34*3];
    int tid = threadIdx.x;
    int bx = blockIdx.x, oy = blockIdx.y, n = blockIdx.z;
    if (bx == 0 && oy == 0 && n == 0 && tid == 0) g_loss = 0.0f;
    for (int i = tid; i < 6144; i += 128) ws[i] = w[i];
    int x0 = bx * 16;
    for (int i = tid; i < 4*34*3; i += 128) {
        int r = i / (34*3); int rem = i - r*(34*3); int c = rem / 3; int ch = rem % 3;
        int gy = 2*oy - 1 + r;
        int gx = 2*x0 - 1 + c;
        float v = 0.0f;
        if (gy >= 0 && gy < H0 && gx >= 0 && gx < W0) v = x[((n*H0+gy)*W0+gx)*CIN + ch];
        ins[i] = v;
    }
    __syncthreads();
    int co = tid;
    float bias = b[co];
    u64 acc2[8];
#pragma unroll
    for (int pp = 0; pp < 8; pp++) acc2[pp] = pack2(bias, bias);
    for (int ky = 0; ky < 4; ky++) {
        for (int kx = 0; kx < 4; kx++) {
#pragma unroll
            for (int ci = 0; ci < 3; ci++) {
                float wv = ws[((ky*4+kx)*3+ci)*128 + co];
                u64 wvv = splat2(wv);
#pragma unroll
                for (int pp = 0; pp < 8; pp++) {
                    u64 av = pack2(ins[(ky*34 + 4*pp + kx)*3 + ci],
                                   ins[(ky*34 + 4*pp + 2 + kx)*3 + ci]);
                    ffma2(acc2[pp], av, wvv);
                }
            }
        }
    }
#pragma unroll
    for (int pp = 0; pp < 8; pp++) {
        float v0, v1; unpack2(acc2[pp], v0, v1);
        g_h1[((n*H1v+oy)*W1v + x0 + 2*pp)*HID + co]     = gelu_f(v0);
        g_h1[((n*H1v+oy)*W1v + x0 + 2*pp + 1)*HID + co] = gelu_f(v1);
    }
}

// ================= conv2 (R5 GEMM-tiled, f32x2) + gelu + 1x1: h1 -> z_e =================
__global__ void __launch_bounds__(128) k_conv2(const float* __restrict__ w2, const float* __restrict__ b2,
                                               const float* __restrict__ w3, const float* __restrict__ b3) {
    __shared__ float sm[2112 + 8192];
    float* ins = sm;
    float* Bs  = sm + 2112;
    float* h2s = sm;
    int tid = threadIdx.x;
    int oy = blockIdx.x, n = blockIdx.y;
    int pa = tid & 7, cg = tid >> 3;
    int co0 = cg * 8;
    u64 acc2[8][4];
    {
        float4 b0 = *reinterpret_cast<const float4*>(&b2[co0]);
        float4 b1 = *reinterpret_cast<const float4*>(&b2[co0+4]);
        u64 p0 = pack2(b0.x,b0.y), p1 = pack2(b0.z,b0.w);
        u64 p2 = pack2(b1.x,b1.y), p3 = pack2(b1.z,b1.w);
#pragma unroll
        for (int j = 0; j < 8; j++) { acc2[j][0]=p0; acc2[j][1]=p1; acc2[j][2]=p2; acc2[j][3]=p3; }
    }
    int axbase = 2 * pa;
#pragma unroll 1
    for (int ch = 0; ch < 32; ch++) {
        int ci0 = ch * 4;
        for (int i = tid; i < 520; i += 128) {
            int r = i / 130; int ixl = i - r*130;
            int iy = 2*oy - 1 + r;
            int ix = ixl - 1;
            float4 v = make_float4(0,0,0,0);
            if (iy >= 0 && iy < H1v && ix >= 0 && ix < W1v)
                v = *reinterpret_cast<const float4*>(&g_h1[((n*H1v+iy)*W1v+ix)*HID + ci0]);
            float* dst = &ins[(r*4)*132 + ixl];
            dst[0] = v.x; dst[132] = v.y; dst[264] = v.z; dst[396] = v.w;
        }
        for (int i = tid; i < 2048; i += 128) {
            int co4 = i & 31; int cik = (i >> 5) & 3; int tap = i >> 7;
            float4 wv = *reinterpret_cast<const float4*>(&w2[((tap*HID) + ci0 + cik)*HID + co4*4]);
            *reinterpret_cast<float4*>(&Bs[(tap*4+cik)*128 + co4*4]) = wv;
        }
        __syncthreads();
        for (int tap = 0; tap < 16; tap++) {
            int kx = tap & 3; int row = tap >> 2;
#pragma unroll
            for (int cik = 0; cik < 4; cik++) {
                const u64* bp = reinterpret_cast<const u64*>(&Bs[(tap*4+cik)*128 + co0]);
                u64 w01 = bp[0], w23 = bp[1], w45 = bp[2], w67 = bp[3];
                const float* ap = &ins[(row*4+cik)*132 + axbase + kx];
                float a0 = ap[0],  a1 = ap[16], a2 = ap[32], a3 = ap[48];
                float a4 = ap[64], a5 = ap[80], a6 = ap[96], a7 = ap[112];
                FFMA2_8(0,a0) FFMA2_8(1,a1) FFMA2_8(2,a2) FFMA2_8(3,a3)
                FFMA2_8(4,a4) FFMA2_8(5,a5) FFMA2_8(6,a6) FFMA2_8(7,a7)
            }
        }
        __syncthreads();
    }
#pragma unroll
    for (int j = 0; j < 8; j++) {
        int ox = pa + 8*j;
        float f0,f1,f2,f3,f4,f5,f6,f7;
        unpack2(acc2[j][0], f0, f1); unpack2(acc2[j][1], f2, f3);
        unpack2(acc2[j][2], f4, f5); unpack2(acc2[j][3], f6, f7);
        float4 o0 = make_float4(gelu_f(f0), gelu_f(f1), gelu_f(f2), gelu_f(f3));
        float4 o1 = make_float4(gelu_f(f4), gelu_f(f5), gelu_f(f6), gelu_f(f7));
        *reinterpret_cast<float4*>(&h2s[ox*132 + co0])     = o0;
        *reinterpret_cast<float4*>(&h2s[ox*132 + co0 + 4]) = o1;
    }
    __syncthreads();
    {
        int px = tid >> 1;
        int e0 = (tid & 1) * 32;
        u64 z2[16];
#pragma unroll
        for (int u = 0; u < 8; u++) {
            float4 bb = *reinterpret_cast<const float4*>(&b3[e0 + 4*u]);
            z2[2*u]   = pack2(bb.x, bb.y);
            z2[2*u+1] = pack2(bb.z, bb.w);
        }
#pragma unroll 4
        for (int ci = 0; ci < 128; ci++) {
            float hv = h2s[px*132 + ci];
            u64 s = splat2(hv);
#pragma unroll
            for (int u = 0; u < 8; u++) {
                float4 wv = *reinterpret_cast<const float4*>(&w3[ci*EMB + e0 + 4*u]);
                ffma2(z2[2*u],   s, pack2(wv.x, wv.y));
                ffma2(z2[2*u+1], s, pack2(wv.z, wv.w));
            }
        }
        float* dst = &g_ze[((n*H2v+oy)*W2v + px)*EMB + e0];
#pragma unroll
        for (int u = 0; u < 8; u++) {
            float f0,f1,f2,f3;
            unpack2(z2[2*u], f0, f1); unpack2(z2[2*u+1], f2, f3);
            *reinterpret_cast<float4*>(dst + 4*u) = make_float4(f0, f1, f2, f3);
        }
    }
}

// ================= VQ =================
#define CSTR 68
__global__ void k_vq(const float* __restrict__ cb, float* __restrict__ dout) {
    __shared__ float cs[64*CSTR];
    __shared__ float e2s[64];
    __shared__ float bval[128];
    __shared__ int   bidx[128];
    __shared__ int   widx[16];
    __shared__ float lred[128];
    int tid = threadIdx.x;
    int pb = blockIdx.x * 16;
    int p = tid & 15;
    int g = tid >> 4;
    float4 z4[16];
    const float* zp = &g_ze[(pb + p)*EMB];
#pragma unroll
    for (int i = 0; i < 16; i++) z4[i] = *reinterpret_cast<const float4*>(&zp[4*i]);
    float best = 3.4e38f; int bi = 0;
    for (int ch = 0; ch < 16; ch++) {
        for (int i = tid; i < 64*16; i += 128) {
            int cj = i >> 4; int d4 = i & 15;
            float4 v = *reinterpret_cast<const float4*>(&cb[(ch*64+cj)*EMB + 4*d4]);
            *reinterpret_cast<float4*>(&cs[cj*CSTR + 4*d4]) = v;
        }
        __syncthreads();
        if (tid < 64) {
            float s = 0.0f;
#pragma unroll 8
            for (int d = 0; d < 64; d++) { float c = cs[tid*CSTR + d]; s = fmaf(c, c, s); }
            e2s[tid] = s;
        }
        __syncthreads();
#pragma unroll
        for (int j = 0; j < 8; j++) {
            int cj = g*8 + j;
            const float* cp = &cs[cj*CSTR];
            float dot = 0.0f;
#pragma unroll
            for (int i = 0; i < 16; i++) {
                float4 c = *reinterpret_cast<const float4*>(&cp[4*i]);
                dot = fmaf(z4[i].x, c.x, dot); dot = fmaf(z4[i].y, c.y, dot);
                dot = fmaf(z4[i].z, c.z, dot); dot = fmaf(z4[i].w, c.w, dot);
            }
            float dist = e2s[cj] - 2.0f*dot;
            int gidx = ch*64 + cj;
            if (dist < best || (dist == best && gidx < bi)) { best = dist; bi = gidx; }
        }
        __syncthreads();
    }
    bval[tid] = best; bidx[tid] = bi;
    __syncthreads();
    if (tid < 16) {
        float bb = bval[tid]; int bbi = bidx[tid];
        for (int k = 1; k < 8; k++) {
            float v = bval[tid + 16*k]; int vi = bidx[tid + 16*k];
            if (v < bb || (v == bb && vi < bbi)) { bb = v; bbi = vi; }
        }
        widx[tid] = bbi;
        dout[TOK_OFF + pb + tid] = (float)bbi;
    }
    __syncthreads();
    int idx = widx[p];
    float lsum = 0.0f;
    const float* cq = &cb[idx*EMB + g*8];
    const float* ze = &g_ze[(pb + p)*EMB + g*8];
    float*       zs = &g_zst[(pb + p)*EMB + g*8];
#pragma unroll
    for (int d = 0; d < 8; d++) {
        float zq = cq[d]; float z = ze[d];
        float diff = zq - z;
        zs[d] = z + diff;
        lsum = fmaf(diff, diff, lsum);
    }
    lred[tid] = lsum;
    __syncthreads();
    for (int s = 64; s > 0; s >>= 1) {
        if (tid < s) lred[tid] += lred[tid + s];
        __syncthreads();
    }
    if (tid == 0) atomicAdd(&g_loss, lred[0]);
}

// ================= WMMA tf32 transposed-conv (K=64 chunks, pre-converted) ===
// CTA: one parity tile. M=128 (2 out rows x 64 same-parity px), N=128 co,
// K = 2kyi*2kxi*CI in chunks of 64. 256 threads = 8 warps (4m x 2n).
template<int CI, int HIN, int WIN, bool RGB>
__global__ void __launch_bounds__(256, 2) k_convt_wmma(
    const float* __restrict__ src, const float* __restrict__ wt,
    const float* __restrict__ bias,
    const float* __restrict__ w3, const float* __restrict__ b3,
    float* __restrict__ dst)
{
    constexpr int CIC64 = CI / 64;
    constexpr int NCH   = 4 * CIC64;
    constexpr int HOUT  = 2 * HIN;
    constexpr int WOUT  = 2 * WIN;

    extern __shared__ float smf[];
    float* As    = smf;             // 128*68 = 8704
    float* Bs    = smf + 8704;      // 64*132 = 8448
    float* Cs    = smf;             // epilogue reuse: 128*132 = 16896
    float* biass = smf + 17152;     // 128
    float* w3s   = smf + 17280;     // 384
    float* b3s   = smf + 17664;     // 3

    int tid = threadIdx.x;
    int bx = blockIdx.x, pr = blockIdx.y, n = blockIdx.z;
    int t  = bx & 1;
    int xh = bx >> 1;
    int oy = 4*(pr >> 1) + (pr & 1);          // rows oy, oy+2
    int x0 = xh * 128;
    int xhalf = x0 >> 1;
    int kyA = oy & 1;
    int iy0 = (oy + kyA - 2) >> 1;

    for (int i = tid; i < 128; i += 256) biass[i] = bias[i];
    if (RGB) {
        for (int i = tid; i < 384; i += 256) w3s[i] = w3[i];
        if (tid < 3) b3s[tid] = b3[tid];
    }

    int wid = tid >> 5;
    int m0 = (wid & 3) * 32;
    int n0 = (wid >> 2) * 64;

    wmma::fragment<wmma::accumulator, 16, 16, 8, float> acc[2][4];
#pragma unroll
    for (int im = 0; im < 2; im++)
#pragma unroll
        for (int in = 0; in < 4; in++) wmma::fill_fragment(acc[im][in], 0.0f);

#pragma unroll 1
    for (int c = 0; c < NCH; c++) {
        int kyi = c / (2*CIC64);
        int kxi = (c / CIC64) & 1;
        int ci0 = (c % CIC64) * 64;
        __syncthreads();
        // stage A: 128 rows x 64 floats, tf32-rounded at store
        {
            int xb = xhalf + t + kxi - 1;
#pragma unroll
            for (int q = 0; q < 8; q++) {
                int u = tid + q*256;
                int m = u >> 4, c16 = u & 15;
                int h = m >> 6, j = m & 63;
                int y = iy0 + h + kyi;
                int col = xb + j;
                float4 v = make_float4(0,0,0,0);
                if (y >= 0 && y < HIN && col >= 0 && col < WIN)
                    v = *reinterpret_cast<const float4*>(
                        &src[((size_t)((n*HIN + y)*WIN + col))*CI + ci0 + 4*c16]);
                v.x = tf32r(v.x); v.y = tf32r(v.y); v.z = tf32r(v.z); v.w = tf32r(v.w);
                *reinterpret_cast<float4*>(&As[m*68 + 4*c16]) = v;
            }
        }
        // stage B: 64 k-rows x 128 co (pre-rounded weights)
        {
            int k0 = ((kyA + 2*kyi)*4 + (t + 2*kxi))*CI + ci0;
#pragma unroll
            for (int q = 0; q < 8; q++) {
                int u = tid + q*256;
                int kk = u >> 5, c32 = u & 31;
                float4 v = *reinterpret_cast<const float4*>(&wt[(size_t)(k0 + kk)*128 + 4*c32]);
                *reinterpret_cast<float4*>(&Bs[kk*132 + 4*c32]) = v;
            }
        }
        __syncthreads();
#pragma unroll
        for (int ks = 0; ks < 8; ks++) {
            int kk = ks * 8;
            wmma::fragment<wmma::matrix_a, 16, 16, 8, wmma::precision::tf32, wmma::row_major> af[2];
#pragma unroll
            for (int im = 0; im < 2; im++)
                wmma::load_matrix_sync(af[im], &As[(m0 + 16*im)*68 + kk], 68);
#pragma unroll
            for (int in = 0; in < 4; in++) {
                wmma::fragment<wmma::matrix_b, 16, 16, 8, wmma::precision::tf32, wmma::row_major> bf;
                wmma::load_matrix_sync(bf, &Bs[kk*132 + n0 + 16*in], 132);
#pragma unroll
                for (int im = 0; im < 2; im++)
                    wmma::mma_sync(acc[im][in], af[im], bf, acc[im][in]);
            }
        }
    }
    __syncthreads();
#pragma unroll
    for (int im = 0; im < 2; im++)
#pragma unroll
        for (int in = 0; in < 4; in++)
            wmma::store_matrix_sync(&Cs[(m0 + 16*im)*132 + n0 + 16*in],
                                    acc[im][in], 132, wmma::mem_row_major);
    __syncthreads();
    // epilogue
    {
        int m = tid >> 1;
        int half = tid & 1;
        int h = m >> 6, j = m & 63;
        int row = oy + 2*h;
        int ox = x0 + 2*j + t;
        const float* cp = &Cs[m*132 + half*64];
        if (RGB) {
            float r = 0.0f, g = 0.0f, bl = 0.0f;
#pragma unroll 8
            for (int kk = 0; kk < 64; kk++) {
                int cc = half*64 + kk;
                float gv = gelu_f(cp[kk] + biass[cc]);
                r  = fmaf(gv, w3s[cc*3+0], r);
                g  = fmaf(gv, w3s[cc*3+1], g);
                bl = fmaf(gv, w3s[cc*3+2], bl);
            }
            r  += __shfl_xor_sync(0xffffffffu, r, 1);
            g  += __shfl_xor_sync(0xffffffffu, g, 1);
            bl += __shfl_xor_sync(0xffffffffu, bl, 1);
            if (half == 0) {
                float* dp = dst + ((size_t)((n*HOUT + row)*WOUT + ox))*3;
                dp[0] = r + b3s[0];
                dp[1] = g + b3s[1];
                dp[2] = bl + b3s[2];
            }
        } else {
            float* dp = dst + ((size_t)((n*HOUT + row)*WOUT + ox))*128 + half*64;
#pragma unroll
            for (int k4 = 0; k4 < 16; k4++) {
                float4 o;
                o.x = gelu_f(cp[4*k4+0] + biass[half*64 + 4*k4+0]);
                o.y = gelu_f(cp[4*k4+1] + biass[half*64 + 4*k4+1]);
                o.z = gelu_f(cp[4*k4+2] + biass[half*64 + 4*k4+2]);
                o.w = gelu_f(cp[4*k4+3] + biass[half*64 + 4*k4+3]);
                *reinterpret_cast<float4*>(dp + 4*k4) = o;
            }
        }
    }
}

// ================= finalize losses =================
__global__ void k_final(float* __restrict__ dout) {
    float l = g_loss / (float)(TOK_ELEMS * EMB);
    dout[LOSS_OFF]     = l;
    dout[LOSS_OFF + 1] = l;
}

// ================= launch =================
extern "C" void kernel_launch(void* const* d_in, const int* in_sizes, int n_in,
                              void* d_out, int out_size) {
    const float* x      = (const float*)d_in[0];
    const float* enc_w1 = (const float*)d_in[1];
    const float* enc_b1 = (const float*)d_in[2];
    const float* enc_w2 = (const float*)d_in[3];
    const float* enc_b2 = (const float*)d_in[4];
    const float* enc_w3 = (const float*)d_in[5];
    const float* enc_b3 = (const float*)d_in[6];
    const float* cb     = (const float*)d_in[7];
    const float* dec_w1 = (const float*)d_in[8];
    const float* dec_b1 = (const float*)d_in[9];
    const float* dec_w2 = (const float*)d_in[10];
    const float* dec_b2 = (const float*)d_in[11];
    const float* dec_w3 = (const float*)d_in[12];
    const float* dec_b3 = (const float*)d_in[13];
    float* out = (float*)d_out;

    float* wt1p; cudaGetSymbolAddress((void**)&wt1p, g_wt1);
    float* wt2p; cudaGetSymbolAddress((void**)&wt2p, g_wt2);
    float* zstp; cudaGetSymbolAddress((void**)&zstp, g_zst);
    float* g1p;  cudaGetSymbolAddress((void**)&g1p, g_g1);

    const int smem_dec = 17667 * 4;   // 70668 B
    static int smem_set = 0;
    if (!smem_set) {
        cudaFuncSetAttribute(k_convt_wmma<64, 64, 64, false>,
                             cudaFuncAttributeMaxDynamicSharedMemorySize, smem_dec);
        cudaFuncSetAttribute(k_convt_wmma<128, 128, 128, true>,
                             cudaFuncAttributeMaxDynamicSharedMemorySize, smem_dec);
        smem_set = 1;
    }

    k_prep_tf32<<<512, 256>>>(dec_w1, wt1p, 131072);
    k_prep_tf32<<<1024, 256>>>(dec_w2, wt2p, 262144);

    k_conv1<<<dim3(8, 128, 16), 128>>>(x, enc_w1, enc_b1);
    k_conv2<<<dim3(64, 16), 128>>>(enc_w2, enc_b2, enc_w3, enc_b3);
    k_vq<<<4096, 128>>>(cb, out);

    k_convt_wmma<64, 64, 64, false><<<dim3(2, 64, 16), 256, smem_dec>>>(
        zstp, wt1p, dec_b1, nullptr, nullptr, g1p);
    k_convt_wmma<128, 128, 128, true><<<dim3(4, 128, 16), 256, smem_dec>>>(
        g1p, wt2p, dec_b2, dec_w3, dec_b3, out);
    k_final<<<1, 1>>>(out);
}